// round 2
// baseline (speedup 1.0000x reference)
#include <cuda_runtime.h>
#include <math.h>

// Shapes (fixed by the problem)
#define B_   256
#define Q_   32
#define D_   512
#define E_   300
#define K_   11
#define EPAD 304           // E padded to multiple of 8
#define NCHUNK 38          // EPAD / 8
#define DTILE 128          // docs per block
#define NDBLK 4            // D_/DTILE

// Scratch (device globals are the allowed scratch mechanism)
__device__ float g_qn[B_ * EPAD * Q_];              // normalized queries, [b][e][q], ~10 MB
__device__ float g_part[B_ * NDBLK * Q_ * K_];      // per-(b,dblk) partial kernel sums

// ---------------------------------------------------------------------------
// Kernel A: gather + L2-normalize query embeddings, store transposed [b][e][q]
// ---------------------------------------------------------------------------
__global__ void qnorm_kernel(const int* __restrict__ qtok,
                             const float* __restrict__ emb) {
    __shared__ float buf[Q_ * 301];   // pitch 301 -> conflict-free column reads
    __shared__ float sinv[Q_];
    __shared__ int   stok[Q_];
    const int b   = blockIdx.x;
    const int tid = threadIdx.x;      // 256 threads

    if (tid < Q_) stok[tid] = qtok[b * Q_ + tid];
    __syncthreads();

    for (int idx = tid; idx < Q_ * E_; idx += 256) {
        int q = idx / E_, e = idx % E_;
        buf[q * 301 + e] = emb[(long)stok[q] * E_ + e];
    }
    __syncthreads();

    const int w = tid >> 5, lane = tid & 31;   // 8 warps, 4 rows each
    #pragma unroll
    for (int r = 0; r < 4; ++r) {
        int q = w * 4 + r;
        float s = 0.f;
        for (int e = lane; e < E_; e += 32) { float v = buf[q * 301 + e]; s = fmaf(v, v, s); }
        #pragma unroll
        for (int off = 16; off; off >>= 1) s += __shfl_xor_sync(0xffffffffu, s, off);
        if (lane == 0) sinv[q] = 1.f / (sqrtf(s) + 1e-13f);
    }
    __syncthreads();

    float* out = g_qn + (long)b * EPAD * Q_;
    for (int idx = tid; idx < EPAD * Q_; idx += 256) {
        int e = idx >> 5, q = idx & 31;
        out[idx] = (e < E_) ? buf[q * 301 + e] * sinv[q] : 0.f;
    }
}

// ---------------------------------------------------------------------------
// Main kernel: fused cosine GEMM (32q x 128d per block) + doc norms in-flight
// + Gaussian kernel accumulation. Grid = B_ * NDBLK = 1024 blocks, 128 thr.
// Thread tile: 4q x 8d.
// ---------------------------------------------------------------------------
__global__ __launch_bounds__(128, 4)
void knrm_main_kernel(const int* __restrict__ qtok,
                      const int* __restrict__ dtok,
                      const float* __restrict__ emb,
                      const float* __restrict__ mu,
                      const float* __restrict__ sigma) {
    const int b    = blockIdx.x >> 2;
    const int dblk = blockIdx.x & 3;
    const int d0   = dblk * DTILE;
    const int tid  = threadIdx.x;       // 128
    const int dg   = tid & 15;          // 16 doc groups of 8 docs
    const int qg   = tid >> 4;          // 8 query groups of 4 queries

    __shared__ float s_a[2][8 * Q_];      // A chunk [e][q]
    __shared__ float s_b[2][8 * DTILE];   // B chunk [e][d]
    __shared__ int   s_tok[DTILE];
    __shared__ float s_inv[DTILE];
    __shared__ float s_qm[Q_];
    __shared__ float s_mu[K_], s_i2s[K_];

    const int myTok = dtok[b * D_ + d0 + tid];
    s_tok[tid] = myTok;
    if (tid < Q_) s_qm[tid] = (qtok[b * Q_ + tid] > 0) ? 1.f : 0.f;
    if (tid < K_) {
        float sg = sigma[tid];
        s_mu[tid]  = mu[tid];
        s_i2s[tid] = 1.f / (2.f * sg * sg);
    }

    const float* aBase   = g_qn + (long)b * EPAD * Q_;
    const float* rowBase = emb + (long)myTok * E_;

    // ---- prologue: stage chunk 0 into buffer 0 ----
    {
        if (tid < 64) {
            float4 v = *(const float4*)(aBase + tid * 4);
            *(float4*)&s_a[0][tid * 4] = v;
        }
        float4 v0 = *(const float4*)(rowBase);
        float4 v1 = *(const float4*)(rowBase + 4);
        s_b[0][0 * DTILE + tid] = v0.x;  s_b[0][1 * DTILE + tid] = v0.y;
        s_b[0][2 * DTILE + tid] = v0.z;  s_b[0][3 * DTILE + tid] = v0.w;
        s_b[0][4 * DTILE + tid] = v1.x;  s_b[0][5 * DTILE + tid] = v1.y;
        s_b[0][6 * DTILE + tid] = v1.z;  s_b[0][7 * DTILE + tid] = v1.w;
    }
    __syncthreads();

    float acc[4][8];
    #pragma unroll
    for (int i = 0; i < 4; ++i)
        #pragma unroll
        for (int j = 0; j < 8; ++j) acc[i][j] = 0.f;
    float sq[8] = {0.f, 0.f, 0.f, 0.f, 0.f, 0.f, 0.f, 0.f};

    for (int k = 0; k < NCHUNK; ++k) {
        const int cur = k & 1, nxt = cur ^ 1;
        const bool has = (k + 1 < NCHUNK);
        float4 pa, pb0, pb1;
        if (has) {
            const int e0 = (k + 1) * 8;
            if (tid < 64) pa = *(const float4*)(aBase + e0 * Q_ + tid * 4);
            pb0 = *(const float4*)(rowBase + e0);
            if (k + 1 < 37) pb1 = *(const float4*)(rowBase + e0 + 4);
            else            pb1 = make_float4(0.f, 0.f, 0.f, 0.f);
        }
        #pragma unroll
        for (int e = 0; e < 8; ++e) {
            const float4 a4  = *(const float4*)&s_a[cur][e * Q_   + (qg << 2)];
            const float4 b40 = *(const float4*)&s_b[cur][e * DTILE + (dg << 3)];
            const float4 b41 = *(const float4*)&s_b[cur][e * DTILE + (dg << 3) + 4];
            const float av[4] = {a4.x, a4.y, a4.z, a4.w};
            const float bv[8] = {b40.x, b40.y, b40.z, b40.w, b41.x, b41.y, b41.z, b41.w};
            #pragma unroll
            for (int i = 0; i < 4; ++i)
                #pragma unroll
                for (int j = 0; j < 8; ++j)
                    acc[i][j] = fmaf(av[i], bv[j], acc[i][j]);
            if (qg == 0) {
                #pragma unroll
                for (int j = 0; j < 8; ++j) sq[j] = fmaf(bv[j], bv[j], sq[j]);
            }
        }
        if (has) {
            if (tid < 64) *(float4*)&s_a[nxt][tid * 4] = pa;
            s_b[nxt][0 * DTILE + tid] = pb0.x;  s_b[nxt][1 * DTILE + tid] = pb0.y;
            s_b[nxt][2 * DTILE + tid] = pb0.z;  s_b[nxt][3 * DTILE + tid] = pb0.w;
            s_b[nxt][4 * DTILE + tid] = pb1.x;  s_b[nxt][5 * DTILE + tid] = pb1.y;
            s_b[nxt][6 * DTILE + tid] = pb1.z;  s_b[nxt][7 * DTILE + tid] = pb1.w;
        }
        __syncthreads();
    }

    // ---- doc inverse norms (computed by qg==0 threads) ----
    if (qg == 0) {
        #pragma unroll
        for (int j = 0; j < 8; ++j)
            s_inv[(dg << 3) + j] = 1.f / (sqrtf(sq[j]) + 1e-13f);
    }
    __syncthreads();

    // ---- Gaussian kernel epilogue: accumulate pk[q][k] over this thread's 8 docs
    float pk[4][K_];
    #pragma unroll
    for (int i = 0; i < 4; ++i)
        #pragma unroll
        for (int kk = 0; kk < K_; ++kk) pk[i][kk] = 0.f;

    #pragma unroll
    for (int j = 0; j < 8; ++j) {
        const int d = (dg << 3) + j;
        const float inv = s_inv[d];
        const float dm  = (s_tok[d] > 0) ? 1.f : 0.f;
        #pragma unroll
        for (int i = 0; i < 4; ++i) {
            const float m = dm * s_qm[(qg << 2) + i];
            const float c = acc[i][j] * inv * m;      // cosine_masked
            #pragma unroll
            for (int kk = 0; kk < K_; ++kk) {
                const float diff = c - s_mu[kk];
                pk[i][kk] = fmaf(m, __expf(-diff * diff * s_i2s[kk]), pk[i][kk]);
            }
        }
    }

    // ---- reduce across the 16 doc-groups (each qg group = one half-warp) ----
    #pragma unroll
    for (int i = 0; i < 4; ++i) {
        #pragma unroll
        for (int kk = 0; kk < K_; ++kk) {
            float v = pk[i][kk];
            v += __shfl_xor_sync(0xffffffffu, v, 8);
            v += __shfl_xor_sync(0xffffffffu, v, 4);
            v += __shfl_xor_sync(0xffffffffu, v, 2);
            v += __shfl_xor_sync(0xffffffffu, v, 1);
            pk[i][kk] = v;
        }
    }
    if (dg == 0) {
        float* gp = g_part + ((long)blockIdx.x * Q_ + (qg << 2)) * K_;
        #pragma unroll
        for (int i = 0; i < 4; ++i)
            #pragma unroll
            for (int kk = 0; kk < K_; ++kk)
                gp[i * K_ + kk] = pk[i][kk];
    }
}

// ---------------------------------------------------------------------------
// Final kernel: combine 4 d-block partials, log-pool, dense layer. 1 block / b.
// ---------------------------------------------------------------------------
__global__ void knrm_final_kernel(const int* __restrict__ qtok,
                                  const float* __restrict__ w,
                                  const float* __restrict__ bias,
                                  float* __restrict__ out) {
    const int b   = blockIdx.x;
    const int tid = threadIdx.x;   // 128
    __shared__ float s_w[K_];
    __shared__ float red[4];
    if (tid < K_) s_w[tid] = w[tid];
    __syncthreads();

    float sum = 0.f;
    for (int idx = tid; idx < Q_ * K_; idx += 128) {
        const int q = idx / K_, kk = idx % K_;
        float s = 0.f;
        #pragma unroll
        for (int db = 0; db < NDBLK; ++db)
            s += g_part[(((long)(b * NDBLK + db)) * Q_ + q) * K_ + kk];
        const float qm = (qtok[b * Q_ + q] > 0) ? 1.f : 0.f;
        sum += 0.01f * __logf(fmaxf(s, 1e-10f)) * qm * s_w[kk];
    }
    #pragma unroll
    for (int off = 16; off; off >>= 1) sum += __shfl_xor_sync(0xffffffffu, sum, off);
    if ((tid & 31) == 0) red[tid >> 5] = sum;
    __syncthreads();
    if (tid == 0) out[b] = red[0] + red[1] + red[2] + red[3] + bias[0];
}

// ---------------------------------------------------------------------------
extern "C" void kernel_launch(void* const* d_in, const int* in_sizes, int n_in,
                              void* d_out, int out_size) {
    const int*   qtok  = (const int*)d_in[0];    // [256,32]
    const int*   dtok  = (const int*)d_in[1];    // [256,512]
    const float* emb   = (const float*)d_in[2];  // [100000,300]
    const float* w     = (const float*)d_in[3];  // [1,11]
    const float* bias  = (const float*)d_in[4];  // [1]
    const float* mu    = (const float*)d_in[5];  // [11]
    const float* sigma = (const float*)d_in[6];  // [11]
    float* out = (float*)d_out;                  // [256]

    qnorm_kernel<<<B_, 256>>>(qtok, emb);
    knrm_main_kernel<<<B_ * NDBLK, 128>>>(qtok, dtok, emb, mu, sigma);
    knrm_final_kernel<<<B_, 128>>>(qtok, w, bias, out);
}

// round 4
// speedup vs baseline: 1.1261x; 1.1261x over previous
#include <cuda_runtime.h>
#include <math.h>

// Shapes (fixed by the problem)
#define B_   256
#define Q_   32
#define D_   512
#define E_   300
#define K_   11
#define EPAD 304           // E padded to multiple of 8
#define NCHUNK 38          // EPAD / 8
#define DTILE 256          // docs per block
#define NDBLK 2            // D_/DTILE

typedef unsigned long long u64;

// Packed fp32x2 FMA (Blackwell sm_103a): d.lo=a.lo*b.lo+d.lo, d.hi=a.hi*b.hi+d.hi
#define FMA2(d, a, b) asm("fma.rn.f32x2 %0, %1, %2, %3;" : "=l"(d) : "l"(a), "l"(b), "l"(d))
#define EX2F(r, x)    asm("ex2.approx.f32 %0, %1;" : "=f"(r) : "f"(x))

__device__ float g_qn[B_ * EPAD * Q_];          // normalized queries [b][e][q]
__device__ float g_part[B_ * NDBLK * Q_ * K_];  // per-(b,dblk) partial kernel sums

// ---------------------------------------------------------------------------
// Kernel A: gather + L2-normalize query embeddings, store transposed [b][e][q]
// ---------------------------------------------------------------------------
__global__ void qnorm_kernel(const int* __restrict__ qtok,
                             const float* __restrict__ emb) {
    __shared__ float buf[Q_ * 308];   // pitch 308 (float4-aligned, mild conflicts)
    __shared__ float sinv[Q_];
    __shared__ int   stok[Q_];
    const int b   = blockIdx.x;
    const int tid = threadIdx.x;      // 256 threads

    if (tid < Q_) stok[tid] = qtok[b * Q_ + tid];
    __syncthreads();

    // vectorized gather: 32 rows x 75 float4 (E=300)
    for (int idx = tid; idx < Q_ * 75; idx += 256) {
        int q = idx / 75, v = idx % 75;
        float4 x = *(const float4*)(emb + (long)stok[q] * E_ + v * 4);
        *(float4*)&buf[q * 308 + v * 4] = x;
    }
    // zero-pad e=300..307 of each row (2 float4 per row, 64 threads)
    if (tid < Q_ * 2) {
        int q = tid >> 1, o = (tid & 1) * 4;
        *(float4*)&buf[q * 308 + 300 + o] = make_float4(0.f, 0.f, 0.f, 0.f);
    }
    __syncthreads();

    const int w = tid >> 5, lane = tid & 31;   // 8 warps, 4 rows each
    #pragma unroll
    for (int r = 0; r < 4; ++r) {
        int q = w * 4 + r;
        float s = 0.f;
        for (int e = lane; e < E_; e += 32) { float v = buf[q * 308 + e]; s = fmaf(v, v, s); }
        #pragma unroll
        for (int off = 16; off; off >>= 1) s += __shfl_xor_sync(0xffffffffu, s, off);
        if (lane == 0) sinv[q] = 1.f / (sqrtf(s) + 1e-13f);
    }
    __syncthreads();

    float* out = g_qn + (long)b * EPAD * Q_;
    for (int idx = tid; idx < EPAD * Q_; idx += 256) {
        int e = idx >> 5, q = idx & 31;
        out[idx] = buf[q * 308 + e] * sinv[q];   // rows 300..303 are zero
    }
}

// ---------------------------------------------------------------------------
// Main kernel: FFMA2 cosine GEMM (32q x 256d per block), doc norms in-flight,
// fused Gaussian-kernel epilogue. Grid = B_ * NDBLK = 512 blocks, 128 threads.
// Warp w -> queries 8w..8w+7 (as 4 packed q-pairs); lane l -> docs 8l..8l+7.
// ---------------------------------------------------------------------------
__global__ __launch_bounds__(128, 4)
void knrm_main_kernel(const int* __restrict__ qtok,
                      const int* __restrict__ dtok,
                      const float* __restrict__ emb,
                      const float* __restrict__ mu,
                      const float* __restrict__ sigma) {
    const int b    = blockIdx.x >> 1;
    const int dblk = blockIdx.x & 1;
    const int d0   = dblk * DTILE;
    const int tid  = threadIdx.x;     // 128
    const int w    = tid >> 5;        // warp 0..3 -> query octet
    const int lt   = tid & 31;        // lane -> doc group of 8

    __shared__ float  s_a[2][8 * Q_];          // [buf][e][q]       1 KB x2
    __shared__ float2 s_bd[2][8 * 8 * 32];     // [buf][e][j][lane] dup pairs, 16 KB x2
    __shared__ float  s_inv[8 * 32];           // [j][lane] doc inverse norms
    __shared__ float  s_dm[8 * 32];            // [j][lane] doc masks
    __shared__ float  s_qm[Q_];
    __shared__ float  s_mu[K_], s_nis[K_];     // nis = -log2(e)/(2*sigma^2)

    if (tid < Q_) s_qm[tid] = (qtok[b * Q_ + tid] > 0) ? 1.f : 0.f;
    if (tid < K_) {
        float sg = sigma[tid];
        s_mu[tid]  = mu[tid];
        s_nis[tid] = -1.4426950408889634f / (2.f * sg * sg);
    }

    // doc ownership for staging: docA = 8*lt + w, docB = 8*lt + w + 4
    const int dA = 8 * lt + w, dB = dA + 4;
    const int tokA = dtok[b * D_ + d0 + dA];
    const int tokB = dtok[b * D_ + d0 + dB];
    const float* rowA = emb + (long)tokA * E_;
    const float* rowB = emb + (long)tokB * E_;
    s_dm[w * 32 + lt]       = (tokA > 0) ? 1.f : 0.f;
    s_dm[(w + 4) * 32 + lt] = (tokB > 0) ? 1.f : 0.f;

    const float* aB = g_qn + (long)b * EPAD * Q_;
    const int ea = tid >> 4;            // A-staging: e row 0..7
    const int qa = (tid & 15) * 2;      // A-staging: q pair

    float sqA = 0.f, sqB = 0.f;

    // ---- prologue: stage chunk 0 into buffer 0 ----
    {
        *(float2*)&s_a[0][ea * Q_ + qa] = *(const float2*)(aB + ea * Q_ + qa);
        float4 fa0 = *(const float4*)(rowA);
        float4 fa1 = *(const float4*)(rowA + 4);
        float4 fb0 = *(const float4*)(rowB);
        float4 fb1 = *(const float4*)(rowB + 4);
        float va[8] = {fa0.x, fa0.y, fa0.z, fa0.w, fa1.x, fa1.y, fa1.z, fa1.w};
        float vb[8] = {fb0.x, fb0.y, fb0.z, fb0.w, fb1.x, fb1.y, fb1.z, fb1.w};
        #pragma unroll
        for (int e = 0; e < 8; ++e) {
            s_bd[0][(e * 8 + w) * 32 + lt]     = make_float2(va[e], va[e]);
            s_bd[0][(e * 8 + w + 4) * 32 + lt] = make_float2(vb[e], vb[e]);
            sqA = fmaf(va[e], va[e], sqA);
            sqB = fmaf(vb[e], vb[e], sqB);
        }
    }
    __syncthreads();

    u64 acc[4][8];
    #pragma unroll
    for (int p = 0; p < 4; ++p)
        #pragma unroll
        for (int j = 0; j < 8; ++j) acc[p][j] = 0ull;

    for (int k = 0; k < NCHUNK; ++k) {
        const int cur = k & 1;
        const bool has = (k + 1 < NCHUNK);
        float2 pQ; float4 pA0, pA1, pB0, pB1;
        if (has) {
            const int e0 = (k + 1) * 8;
            pQ  = *(const float2*)(aB + (e0 + ea) * Q_ + qa);
            pA0 = *(const float4*)(rowA + e0);
            pB0 = *(const float4*)(rowB + e0);
            if (k + 1 < NCHUNK - 1) {
                pA1 = *(const float4*)(rowA + e0 + 4);
                pB1 = *(const float4*)(rowB + e0 + 4);
            } else {
                pA1 = make_float4(0.f, 0.f, 0.f, 0.f);
                pB1 = pA1;
            }
        }
        // ---- compute 8 e-steps on buffer `cur` ----
        #pragma unroll
        for (int e = 0; e < 8; ++e) {
            u64 ap[4], bd[8];
            #pragma unroll
            for (int p = 0; p < 4; ++p)          // broadcast: all lanes same addr
                ap[p] = *(const u64*)&s_a[cur][e * Q_ + 8 * w + 2 * p];
            #pragma unroll
            for (int j = 0; j < 8; ++j)          // sequential lane addresses
                bd[j] = *(const u64*)&s_bd[cur][(e * 8 + j) * 32 + lt];
            #pragma unroll
            for (int p = 0; p < 4; ++p)
                #pragma unroll
                for (int j = 0; j < 8; ++j)
                    FMA2(acc[p][j], ap[p], bd[j]);
        }
        // ---- store prefetched chunk into the other buffer ----
        if (has) {
            const int nb = cur ^ 1;
            *(float2*)&s_a[nb][ea * Q_ + qa] = pQ;
            float va[8] = {pA0.x, pA0.y, pA0.z, pA0.w, pA1.x, pA1.y, pA1.z, pA1.w};
            float vb[8] = {pB0.x, pB0.y, pB0.z, pB0.w, pB1.x, pB1.y, pB1.z, pB1.w};
            #pragma unroll
            for (int e = 0; e < 8; ++e) {
                s_bd[nb][(e * 8 + w) * 32 + lt]     = make_float2(va[e], va[e]);
                s_bd[nb][(e * 8 + w + 4) * 32 + lt] = make_float2(vb[e], vb[e]);
                sqA = fmaf(va[e], va[e], sqA);
                sqB = fmaf(vb[e], vb[e], sqB);
            }
        }
        __syncthreads();
    }

    // ---- doc inverse norms ----
    s_inv[w * 32 + lt]       = 1.f / (sqrtf(sqA) + 1e-13f);
    s_inv[(w + 4) * 32 + lt] = 1.f / (sqrtf(sqB) + 1e-13f);
    __syncthreads();

    float invj[8], dmj[8];
    #pragma unroll
    for (int j = 0; j < 8; ++j) {
        invj[j] = s_inv[j * 32 + lt];
        dmj[j]  = s_dm[j * 32 + lt];
    }

    // ---- Gaussian kernel epilogue, per query-pair ----
    #pragma unroll
    for (int qp = 0; qp < 4; ++qp) {
        const int q0 = 8 * w + 2 * qp;
        const float qm0 = s_qm[q0], qm1 = s_qm[q0 + 1];
        float pk[2][K_];
        #pragma unroll
        for (int i = 0; i < 2; ++i)
            #pragma unroll
            for (int kk = 0; kk < K_; ++kk) pk[i][kk] = 0.f;

        #pragma unroll
        for (int j = 0; j < 8; ++j) {
            float2 cv = *(float2*)&acc[qp][j];
            const float m0 = qm0 * dmj[j];
            const float m1 = qm1 * dmj[j];
            const float c0 = cv.x * invj[j] * m0;   // masked cosine
            const float c1 = cv.y * invj[j] * m1;
            #pragma unroll
            for (int kk = 0; kk < K_; ++kk) {
                const float muk = s_mu[kk], nk = s_nis[kk];
                float p0 = c0 - muk, p1 = c1 - muk;
                float a0 = p0 * nk * p0, a1 = p1 * nk * p1;   // log2-domain arg
                float e0, e1;
                EX2F(e0, a0); EX2F(e1, a1);
                pk[0][kk] = fmaf(m0, e0, pk[0][kk]);
                pk[1][kk] = fmaf(m1, e1, pk[1][kk]);
            }
        }
        // reduce across 32 lanes (docs)
        #pragma unroll
        for (int i = 0; i < 2; ++i)
            #pragma unroll
            for (int kk = 0; kk < K_; ++kk) {
                float v = pk[i][kk];
                #pragma unroll
                for (int off = 16; off; off >>= 1) v += __shfl_xor_sync(0xffffffffu, v, off);
                pk[i][kk] = v;
            }
        if (lt == 0) {
            float* gp = g_part + (((long)(b * NDBLK + dblk)) * Q_ + q0) * K_;
            #pragma unroll
            for (int kk = 0; kk < K_; ++kk) { gp[kk] = pk[0][kk]; gp[K_ + kk] = pk[1][kk]; }
        }
    }
}

// ---------------------------------------------------------------------------
// Final kernel: combine 2 d-block partials, log-pool, dense layer. 1 block / b.
// ---------------------------------------------------------------------------
__global__ void knrm_final_kernel(const int* __restrict__ qtok,
                                  const float* __restrict__ w,
                                  const float* __restrict__ bias,
                                  float* __restrict__ out) {
    const int b   = blockIdx.x;
    const int tid = threadIdx.x;   // 128
    __shared__ float s_w[K_];
    __shared__ float red[4];
    if (tid < K_) s_w[tid] = w[tid];
    __syncthreads();

    float sum = 0.f;
    for (int idx = tid; idx < Q_ * K_; idx += 128) {
        const int q = idx / K_, kk = idx % K_;
        float s = 0.f;
        #pragma unroll
        for (int db = 0; db < NDBLK; ++db)
            s += g_part[(((long)(b * NDBLK + db)) * Q_ + q) * K_ + kk];
        const float qm = (qtok[b * Q_ + q] > 0) ? 1.f : 0.f;
        sum += 0.01f * __logf(fmaxf(s, 1e-10f)) * qm * s_w[kk];
    }
    #pragma unroll
    for (int off = 16; off; off >>= 1) sum += __shfl_xor_sync(0xffffffffu, sum, off);
    if ((tid & 31) == 0) red[tid >> 5] = sum;
    __syncthreads();
    if (tid == 0) out[b] = red[0] + red[1] + red[2] + red[3] + bias[0];
}

// ---------------------------------------------------------------------------
extern "C" void kernel_launch(void* const* d_in, const int* in_sizes, int n_in,
                              void* d_out, int out_size) {
    const int*   qtok  = (const int*)d_in[0];    // [256,32]
    const int*   dtok  = (const int*)d_in[1];    // [256,512]
    const float* emb   = (const float*)d_in[2];  // [100000,300]
    const float* w     = (const float*)d_in[3];  // [1,11]
    const float* bias  = (const float*)d_in[4];  // [1]
    const float* mu    = (const float*)d_in[5];  // [11]
    const float* sigma = (const float*)d_in[6];  // [11]
    float* out = (float*)d_out;                  // [256]

    qnorm_kernel<<<B_, 256>>>(qtok, emb);
    knrm_main_kernel<<<B_ * NDBLK, 128>>>(qtok, dtok, emb, mu, sigma);
    knrm_final_kernel<<<B_, 128>>>(qtok, w, bias, out);
}

// round 6
// speedup vs baseline: 2.1071x; 1.8712x over previous
#include <cuda_runtime.h>
#include <cuda_fp16.h>
#include <cstdint>
#include <math.h>

#define B_     256
#define Q_     32
#define D_     512
#define E_     300
#define K_     11
#define MT_    128      // docs per CTA
#define NMT    4        // doc tiles (D_/MT_)
#define NCH    5        // K chunks of 64 (K padded 300 -> 320)
#define APITCH 72       // A tile pitch in halves (64 + 8 pad, conflict-free)
#define BPITCH 328      // B tile pitch in halves (320 + 8, conflict-free)

#define EX2F(r, x) asm("ex2.approx.f32 %0, %1;" : "=f"(r) : "f"(x))

__device__ float g_part[B_ * NMT * Q_ * K_];

struct SM {
    union {
        __align__(16) __half A[2][MT_ * APITCH];   // 36864 B (double-buffered doc chunks)
        float spart[8][Q_][12];                    // 12288 B (epilogue partials)
    } u;
    __align__(16) __half Bq[Q_ * BPITCH];          // 20992 B (normalized queries, fp16)
    float inv[MT_];
    float dm[MT_];
    float qm[Q_];
    int   qt[Q_];
    int   dtk[MT_];
    float mu[K_], nis[K_];
};

__device__ __forceinline__ void hmma16816(float* c, const uint32_t* a, const uint32_t* b) {
    asm volatile("mma.sync.aligned.m16n8k16.row.col.f32.f16.f16.f32 "
        "{%0,%1,%2,%3}, {%4,%5,%6,%7}, {%8,%9}, {%0,%1,%2,%3};"
        : "+f"(c[0]), "+f"(c[1]), "+f"(c[2]), "+f"(c[3])
        : "r"(a[0]), "r"(a[1]), "r"(a[2]), "r"(a[3]), "r"(b[0]), "r"(b[1]));
}

// ---------------------------------------------------------------------------
// Fused kernel: query gather+norm (in-CTA) -> fp16 HMMA cosine GEMM
// (128 docs x 32 queries, K=304->320) -> Gaussian kernels + exact-match K0.
// grid = 1024 (b, mt), 256 threads (8 warps).
// ---------------------------------------------------------------------------
__global__ void __launch_bounds__(256)
knrm_main_kernel(const int* __restrict__ qtok,
                 const int* __restrict__ dtok,
                 const float* __restrict__ emb,
                 const float* __restrict__ mu,
                 const float* __restrict__ sigma) {
    extern __shared__ char smem_raw[];
    SM& sm = *reinterpret_cast<SM*>(smem_raw);

    const int bi = blockIdx.x, b = bi >> 2, mt = bi & 3;
    const int tid = threadIdx.x, w = tid >> 5, lane = tid & 31;

    // ---- doc ownership: 2 threads per doc row ----
    const int doc = tid >> 1, h = tid & 1;
    const int tokD = dtok[b * D_ + mt * MT_ + doc];
    if (h == 0) { sm.dm[doc] = (tokD > 0) ? 1.f : 0.f; sm.dtk[doc] = tokD; }
    const float* rowD = emb + (long)tokD * E_;

    if (tid < Q_) { int t = qtok[b * Q_ + tid]; sm.qt[tid] = t; sm.qm[tid] = (t > 0) ? 1.f : 0.f; }
    if (tid < K_) {
        float sg = sigma[tid];
        sm.mu[tid]  = mu[tid];
        sm.nis[tid] = -1.4426950408889634f / (2.f * sg * sg);
    }
    __syncthreads();   // sm.qt ready for query gather

    // ---- prefetch doc chunk 0 (issue gmem loads early) ----
    float4 ra[8];
    {
        const int e0 = h * 32;
        #pragma unroll
        for (int i = 0; i < 8; ++i) {
            int e = e0 + i * 4;
            ra[i] = (e < E_) ? *(const float4*)(rowD + e) : make_float4(0.f, 0.f, 0.f, 0.f);
        }
    }

    // ---- query gather + L2-normalize -> fp16 B tile (warp w: queries 4w..4w+3)
    #pragma unroll
    for (int r = 0; r < 4; ++r) {
        const int q = w * 4 + r;
        const float* rowQ = emb + (long)sm.qt[q] * E_;
        float v[10]; float s = 0.f;
        #pragma unroll
        for (int i = 0; i < 10; ++i) {
            int e = lane + 32 * i;
            v[i] = (e < E_) ? rowQ[e] : 0.f;
            s = fmaf(v[i], v[i], s);
        }
        #pragma unroll
        for (int off = 16; off; off >>= 1) s += __shfl_xor_sync(0xffffffffu, s, off);
        const float iv = 1.f / (sqrtf(s) + 1e-13f);
        #pragma unroll
        for (int i = 0; i < 10; ++i) {
            int e = lane + 32 * i;
            if (e < 304) sm.Bq[q * BPITCH + e] = __float2half_rn(v[i] * iv);
        }
        if (lane < 8) sm.Bq[q * BPITCH + 304 + lane * 2] = __half(0.f);
        if (lane < 8) sm.Bq[q * BPITCH + 305 + lane * 2] = __half(0.f);
    }

    // ---- convert+store chunk 0 into A[0], accumulate doc norm ----
    float sq = 0.f;
    {
        __half2* dst = (__half2*)&sm.u.A[0][doc * APITCH + h * 32];
        #pragma unroll
        for (int i = 0; i < 8; ++i) {
            float4 f = ra[i];
            sq = fmaf(f.x, f.x, sq); sq = fmaf(f.y, f.y, sq);
            sq = fmaf(f.z, f.z, sq); sq = fmaf(f.w, f.w, sq);
            dst[i * 2]     = __floats2half2_rn(f.x, f.y);
            dst[i * 2 + 1] = __floats2half2_rn(f.z, f.w);
        }
    }
    __syncthreads();

    // ---- HMMA mainloop: warp w owns docs [16w,16w+16), 4 n-tiles of 8 queries
    float acc[4][4];
    #pragma unroll
    for (int t = 0; t < 4; ++t)
        #pragma unroll
        for (int i = 0; i < 4; ++i) acc[t][i] = 0.f;

    const int arow = 16 * w + (lane >> 2);
    const int acol = (lane & 3) * 2;

    for (int kc = 0; kc < NCH; ++kc) {
        const int cur = kc & 1;
        if (kc + 1 < NCH) {
            const int e0 = (kc + 1) * 64 + h * 32;
            #pragma unroll
            for (int i = 0; i < 8; ++i) {
                int e = e0 + i * 4;
                ra[i] = (e < E_) ? *(const float4*)(rowD + e) : make_float4(0.f, 0.f, 0.f, 0.f);
            }
        }
        const __half* Ab = sm.u.A[cur];
        #pragma unroll
        for (int ks = 0; ks < 4; ++ks) {
            const int kc0 = ks * 16;
            uint32_t a[4];
            a[0] = *(const uint32_t*)&Ab[arow * APITCH + kc0 + acol];
            a[1] = *(const uint32_t*)&Ab[(arow + 8) * APITCH + kc0 + acol];
            a[2] = *(const uint32_t*)&Ab[arow * APITCH + kc0 + acol + 8];
            a[3] = *(const uint32_t*)&Ab[(arow + 8) * APITCH + kc0 + acol + 8];
            const int kg = kc * 64 + kc0;
            #pragma unroll
            for (int t = 0; t < 4; ++t) {
                const int n = t * 8 + (lane >> 2);
                uint32_t bb[2];
                bb[0] = *(const uint32_t*)&sm.Bq[n * BPITCH + kg + acol];
                bb[1] = *(const uint32_t*)&sm.Bq[n * BPITCH + kg + acol + 8];
                hmma16816(acc[t], a, bb);
            }
        }
        if (kc + 1 < NCH) {
            __half2* dst = (__half2*)&sm.u.A[cur ^ 1][doc * APITCH + h * 32];
            #pragma unroll
            for (int i = 0; i < 8; ++i) {
                float4 f = ra[i];
                sq = fmaf(f.x, f.x, sq); sq = fmaf(f.y, f.y, sq);
                sq = fmaf(f.z, f.z, sq); sq = fmaf(f.w, f.w, sq);
                dst[i * 2]     = __floats2half2_rn(f.x, f.y);
                dst[i * 2 + 1] = __floats2half2_rn(f.z, f.w);
            }
        }
        __syncthreads();
    }

    // ---- doc inverse norms ----
    float sqt = sq + __shfl_xor_sync(0xffffffffu, sq, 1);
    if (h == 0) sm.inv[doc] = 1.f / (sqrtf(sqt) + 1e-13f);
    __syncthreads();   // also: all warps done reading A union before spart writes

    // ---- epilogue: Gaussian kernels + exact-match K0, per n-tile ----
    const int doc0 = 16 * w + (lane >> 2), doc1 = doc0 + 8;
    const float iv0 = sm.inv[doc0], dm0 = sm.dm[doc0];
    const float iv1 = sm.inv[doc1], dm1 = sm.dm[doc1];
    const int   tk0 = sm.dtk[doc0], tk1 = sm.dtk[doc1];

    #pragma unroll
    for (int t = 0; t < 4; ++t) {
        const int q0 = t * 8 + (lane & 3) * 2, q1 = q0 + 1;
        const float qm0 = sm.qm[q0], qm1 = sm.qm[q1];
        const int   tq0 = sm.qt[q0], tq1 = sm.qt[q1];
        const float m00 = qm0 * dm0, m01 = qm1 * dm0;
        const float m10 = qm0 * dm1, m11 = qm1 * dm1;
        const float c00 = acc[t][0] * iv0 * m00, c01 = acc[t][1] * iv0 * m01;
        const float c10 = acc[t][2] * iv1 * m10, c11 = acc[t][3] * iv1 * m11;

        float pk0[K_], pk1[K_];
        // kernel 0: exact integer token match (sigma=1e-4 detector)
        pk0[0] = ((tq0 > 0) ? (((tk0 == tq0) ? 1.f : 0.f) + ((tk1 == tq0) ? 1.f : 0.f)) : 0.f);
        pk1[0] = ((tq1 > 0) ? (((tk0 == tq1) ? 1.f : 0.f) + ((tk1 == tq1) ? 1.f : 0.f)) : 0.f);
        #pragma unroll
        for (int k = 1; k < K_; ++k) {
            const float muk = sm.mu[k], nk = sm.nis[k];
            float d00 = c00 - muk, d01 = c01 - muk, d10 = c10 - muk, d11 = c11 - muk;
            float e00, e01, e10, e11;
            EX2F(e00, d00 * nk * d00); EX2F(e01, d01 * nk * d01);
            EX2F(e10, d10 * nk * d10); EX2F(e11, d11 * nk * d11);
            pk0[k] = fmaf(m00, e00, m10 * e10);
            pk1[k] = fmaf(m01, e01, m11 * e11);
        }
        // reduce across the 8 doc-lanes sharing this (lane&3)
        #pragma unroll
        for (int k = 0; k < K_; ++k) {
            float v0 = pk0[k], v1 = pk1[k];
            v0 += __shfl_xor_sync(0xffffffffu, v0, 4);
            v0 += __shfl_xor_sync(0xffffffffu, v0, 8);
            v0 += __shfl_xor_sync(0xffffffffu, v0, 16);
            v1 += __shfl_xor_sync(0xffffffffu, v1, 4);
            v1 += __shfl_xor_sync(0xffffffffu, v1, 8);
            v1 += __shfl_xor_sync(0xffffffffu, v1, 16);
            if (lane < 4) { sm.u.spart[w][q0][k] = v0; sm.u.spart[w][q1][k] = v1; }
        }
    }
    __syncthreads();

    // ---- combine 8 warps, write per-CTA partials ----
    for (int idx = tid; idx < Q_ * K_; idx += 256) {
        const int q = idx / K_, k = idx % K_;
        float s = 0.f;
        #pragma unroll
        for (int ww = 0; ww < 8; ++ww) s += sm.u.spart[ww][q][k];
        g_part[(long)bi * (Q_ * K_) + idx] = s;
    }
}

// ---------------------------------------------------------------------------
// Final kernel: combine 4 doc-tile partials, log-pool, dense. 1 block / batch.
// ---------------------------------------------------------------------------
__global__ void knrm_final_kernel(const int* __restrict__ qtok,
                                  const float* __restrict__ w,
                                  const float* __restrict__ bias,
                                  float* __restrict__ out) {
    const int b = blockIdx.x, tid = threadIdx.x;   // 128
    __shared__ float s_w[K_];
    __shared__ float red[4];
    if (tid < K_) s_w[tid] = w[tid];
    __syncthreads();

    float sum = 0.f;
    for (int idx = tid; idx < Q_ * K_; idx += 128) {
        const int q = idx / K_, kk = idx % K_;
        float s = 0.f;
        #pragma unroll
        for (int m = 0; m < NMT; ++m)
            s += g_part[((long)(b * NMT + m)) * (Q_ * K_) + idx];
        const float qm = (qtok[b * Q_ + q] > 0) ? 1.f : 0.f;
        sum += 0.01f * __logf(fmaxf(s, 1e-10f)) * qm * s_w[kk];
    }
    #pragma unroll
    for (int off = 16; off; off >>= 1) sum += __shfl_xor_sync(0xffffffffu, sum, off);
    if ((tid & 31) == 0) red[tid >> 5] = sum;
    __syncthreads();
    if (tid == 0) out[b] = red[0] + red[1] + red[2] + red[3] + bias[0];
}

// ---------------------------------------------------------------------------
extern "C" void kernel_launch(void* const* d_in, const int* in_sizes, int n_in,
                              void* d_out, int out_size) {
    const int*   qtok  = (const int*)d_in[0];    // [256,32]
    const int*   dtok  = (const int*)d_in[1];    // [256,512]
    const float* emb   = (const float*)d_in[2];  // [100000,300]
    const float* w     = (const float*)d_in[3];  // [1,11]
    const float* bias  = (const float*)d_in[4];  // [1]
    const float* mu    = (const float*)d_in[5];  // [11]
    const float* sigma = (const float*)d_in[6];  // [11]
    float* out = (float*)d_out;                  // [256]

    static bool attr_set = false;
    if (!attr_set) {
        cudaFuncSetAttribute(knrm_main_kernel,
                             cudaFuncAttributeMaxDynamicSharedMemorySize,
                             (int)sizeof(SM));
        attr_set = true;
    }
    knrm_main_kernel<<<B_ * NMT, 256, sizeof(SM)>>>(qtok, dtok, emb, mu, sigma);
    knrm_final_kernel<<<B_, 128>>>(qtok, w, bias, out);
}

// round 10
// speedup vs baseline: 2.2681x; 1.0764x over previous
#include <cuda_runtime.h>
#include <cuda_fp16.h>
#include <cstdint>
#include <math.h>

#define B_     256
#define Q_     32
#define D_     512
#define E_     300
#define K_     11
#define V_     100000
#define EP     320       // padded row length (halves)
#define MT_    128       // docs per CTA
#define NMT    4
#define CH     32        // K-chunk (halves)
#define NCH    10
#define APITCH 40        // chunk pitch (32 + 8 pad halves) = 80 B, conflict-free
#define BPITCH 328       // query pitch (320 + 8 pad halves) = 656 B

#define EX2F(r, x) asm("ex2.approx.f32 %0, %1;" : "=f"(r) : "f"(x))
#define CPA16(dst, src) asm volatile("cp.async.cg.shared.global [%0], [%1], 16;" :: "r"(dst), "l"(src))
#define CP_COMMIT()     asm volatile("cp.async.commit_group;")
#define CP_WAIT(n)      asm volatile("cp.async.wait_group %0;" :: "n"(n))

__device__ __half g_ne[(size_t)V_ * EP];        // normalized fp16 table (64 MB)
__device__ float  g_part[B_ * NMT * Q_ * K_];   // per-(b,mt) partial kernel sums

__device__ __forceinline__ void hmma16816(float* c, const uint32_t* a, const uint32_t* b) {
    asm volatile("mma.sync.aligned.m16n8k16.row.col.f32.f16.f16.f32 "
        "{%0,%1,%2,%3}, {%4,%5,%6,%7}, {%8,%9}, {%0,%1,%2,%3};"
        : "+f"(c[0]), "+f"(c[1]), "+f"(c[2]), "+f"(c[3])
        : "r"(a[0]), "r"(a[1]), "r"(a[2]), "r"(a[3]), "r"(b[0]), "r"(b[1]));
}

// ---------------------------------------------------------------------------
// Pass 1: normalize every embedding row -> fp16, pad 300->320 with zeros.
// Warp per row; grid 12500 x 256.
// ---------------------------------------------------------------------------
__global__ void __launch_bounds__(256)
norm_emb_kernel(const float* __restrict__ emb) {
    const int row  = blockIdx.x * 8 + (threadIdx.x >> 5);
    const int lane = threadIdx.x & 31;
    if (row >= V_) return;
    const float* src = emb + (long)row * E_;
    float2 v[5];
    float s = 0.f;
    #pragma unroll
    for (int i = 0; i < 5; ++i) {
        const int e = 2 * lane + 64 * i;
        if (e < E_) {
            v[i] = *(const float2*)(src + e);
            s = fmaf(v[i].x, v[i].x, s);
            s = fmaf(v[i].y, v[i].y, s);
        } else {
            v[i] = make_float2(0.f, 0.f);
        }
    }
    #pragma unroll
    for (int off = 16; off; off >>= 1) s += __shfl_xor_sync(0xffffffffu, s, off);
    const float iv = 1.f / (sqrtf(s) + 1e-13f);
    __half2* dst = (__half2*)(g_ne + (size_t)row * EP);
    #pragma unroll
    for (int i = 0; i < 5; ++i)
        dst[lane + 32 * i] = __floats2half2_rn(v[i].x * iv, v[i].y * iv);
}

// ---------------------------------------------------------------------------
// Main kernel: fp16 HMMA cosine GEMM on pre-normalized rows, 4-deep cp.async
// pipeline. Grid = 1024 (b, mt), 256 threads (8 warps).
// ---------------------------------------------------------------------------
struct SM {
    union {
        __align__(16) __half A[4][MT_ * APITCH];   // 40960 B (4-buffer K-chunks)
        float spart[8][Q_][12];                    // 12288 B (epilogue partials)
    } u;
    __align__(16) __half Bq[Q_ * BPITCH];          // 20992 B (query tile)
    float dm[MT_];
    int   dtk[MT_];
    float qm[Q_];
    int   qt[Q_];
    float mu[K_], nis[K_];
};

__global__ void __launch_bounds__(256)
knrm_main_kernel(const int* __restrict__ qtok,
                 const int* __restrict__ dtok,
                 const float* __restrict__ mu,
                 const float* __restrict__ sigma) {
    extern __shared__ char smem_raw[];
    SM& sm = *reinterpret_cast<SM*>(smem_raw);

    const int bi = blockIdx.x, b = bi >> 2, mt = bi & 3;
    const int tid = threadIdx.x, w = tid >> 5, lane = tid & 31;

    if (tid < Q_) { int t = qtok[b * Q_ + tid]; sm.qt[tid] = t; sm.qm[tid] = (t > 0) ? 1.f : 0.f; }
    if (tid >= 64 && tid < 64 + K_) {
        const int k = tid - 64;
        float sg = sigma[k];
        sm.mu[k]  = mu[k];
        sm.nis[k] = -1.4426950408889634f / (2.f * sg * sg);
    }
    if (tid >= 128) {
        const int dc = tid - 128;
        int t = dtok[b * D_ + mt * MT_ + dc];
        sm.dtk[dc] = t; sm.dm[dc] = (t > 0) ? 1.f : 0.f;
    }
    __syncthreads();   // tokens visible for async-copy addressing

    const uint32_t aS = (uint32_t)__cvta_generic_to_shared(&sm.u.A[0][0]);
    const uint32_t bS = (uint32_t)__cvta_generic_to_shared(&sm.Bq[0]);
    const char*    ne = (const char*)g_ne;

    // B tile: 32 rows x 40 x 16B = 1280 ops, 5 per thread
    #pragma unroll
    for (int j = 0; j < 5; ++j) {
        const int idx = tid + 256 * j;
        const int q = idx / 40, c = idx % 40;
        CPA16(bS + q * 656 + c * 16, ne + (size_t)sm.qt[q] * 640 + c * 16);
    }
    // A chunk issue: 128 rows x 4 x 16B = 512 ops, 2 per thread
    auto issueA = [&](int kc, int buf) {
        #pragma unroll
        for (int j = 0; j < 2; ++j) {
            const int idx = tid + 256 * j;
            const int dc = idx >> 2, sg = idx & 3;
            CPA16(aS + buf * 10240 + dc * 80 + sg * 16,
                  ne + (size_t)sm.dtk[dc] * 640 + kc * 64 + sg * 16);
        }
    };
    issueA(0, 0); CP_COMMIT();       // group 0 = B + A0
    issueA(1, 1); CP_COMMIT();       // group 1
    issueA(2, 2); CP_COMMIT();       // group 2

    float acc[4][4];
    #pragma unroll
    for (int t = 0; t < 4; ++t)
        #pragma unroll
        for (int i = 0; i < 4; ++i) acc[t][i] = 0.f;

    const int arow = 16 * w + (lane >> 2);
    const int acol = (lane & 3) * 2;

    for (int kc = 0; kc < NCH; ++kc) {
        CP_WAIT(2);
        __syncthreads();
        // issue chunk kc+3 into buf (kc+3)&3 (freed: held kc-1, synced since)
        if (kc + 3 < NCH) issueA(kc + 3, (kc + 3) & 3);
        CP_COMMIT();
        const __half* Ab = sm.u.A[kc & 3];
        #pragma unroll
        for (int ks = 0; ks < 2; ++ks) {
            const int kc0 = ks * 16;
            uint32_t a[4];
            a[0] = *(const uint32_t*)&Ab[arow * APITCH + kc0 + acol];
            a[1] = *(const uint32_t*)&Ab[(arow + 8) * APITCH + kc0 + acol];
            a[2] = *(const uint32_t*)&Ab[arow * APITCH + kc0 + acol + 8];
            a[3] = *(const uint32_t*)&Ab[(arow + 8) * APITCH + kc0 + acol + 8];
            const int kg = kc * CH + kc0;
            #pragma unroll
            for (int t = 0; t < 4; ++t) {
                const int n = t * 8 + (lane >> 2);
                uint32_t bb[2];
                bb[0] = *(const uint32_t*)&sm.Bq[n * BPITCH + kg + acol];
                bb[1] = *(const uint32_t*)&sm.Bq[n * BPITCH + kg + acol + 8];
                hmma16816(acc[t], a, bb);
            }
        }
        __syncthreads();
    }
    __syncthreads();   // all HMMA reads of A done before spart overlays it

    // ---- epilogue: Gaussian kernels + exact-match K0 ----
    const int doc0 = 16 * w + (lane >> 2), doc1 = doc0 + 8;
    const float dm0 = sm.dm[doc0], dm1 = sm.dm[doc1];
    const int   tk0 = sm.dtk[doc0], tk1 = sm.dtk[doc1];

    #pragma unroll
    for (int t = 0; t < 4; ++t) {
        const int q0 = t * 8 + (lane & 3) * 2, q1 = q0 + 1;
        const float qm0 = sm.qm[q0], qm1 = sm.qm[q1];
        const int   tq0 = sm.qt[q0], tq1 = sm.qt[q1];
        const float m00 = qm0 * dm0, m01 = qm1 * dm0;
        const float m10 = qm0 * dm1, m11 = qm1 * dm1;
        const float c00 = acc[t][0] * m00, c01 = acc[t][1] * m01;  // masked cosine
        const float c10 = acc[t][2] * m10, c11 = acc[t][3] * m11;

        float pk0[K_], pk1[K_];
        pk0[0] = ((tq0 > 0) ? (((tk0 == tq0) ? 1.f : 0.f) + ((tk1 == tq0) ? 1.f : 0.f)) : 0.f);
        pk1[0] = ((tq1 > 0) ? (((tk0 == tq1) ? 1.f : 0.f) + ((tk1 == tq1) ? 1.f : 0.f)) : 0.f);
        #pragma unroll
        for (int k = 1; k < K_; ++k) {
            const float muk = sm.mu[k], nk = sm.nis[k];
            float d00 = c00 - muk, d01 = c01 - muk, d10 = c10 - muk, d11 = c11 - muk;
            float e00, e01, e10, e11;
            EX2F(e00, d00 * nk * d00); EX2F(e01, d01 * nk * d01);
            EX2F(e10, d10 * nk * d10); EX2F(e11, d11 * nk * d11);
            pk0[k] = fmaf(m00, e00, m10 * e10);
            pk1[k] = fmaf(m01, e01, m11 * e11);
        }
        #pragma unroll
        for (int k = 0; k < K_; ++k) {
            float v0 = pk0[k], v1 = pk1[k];
            v0 += __shfl_xor_sync(0xffffffffu, v0, 4);
            v0 += __shfl_xor_sync(0xffffffffu, v0, 8);
            v0 += __shfl_xor_sync(0xffffffffu, v0, 16);
            v1 += __shfl_xor_sync(0xffffffffu, v1, 4);
            v1 += __shfl_xor_sync(0xffffffffu, v1, 8);
            v1 += __shfl_xor_sync(0xffffffffu, v1, 16);
            if (lane < 4) { sm.u.spart[w][q0][k] = v0; sm.u.spart[w][q1][k] = v1; }
        }
    }
    __syncthreads();

    for (int idx = tid; idx < Q_ * K_; idx += 256) {
        const int q = idx / K_, k = idx % K_;
        float s = 0.f;
        #pragma unroll
        for (int ww = 0; ww < 8; ++ww) s += sm.u.spart[ww][q][k];
        g_part[(long)bi * (Q_ * K_) + idx] = s;
    }
}

// ---------------------------------------------------------------------------
// Final: warp per batch. Grid 32 x 256.
// ---------------------------------------------------------------------------
__global__ void __launch_bounds__(256)
knrm_final_kernel(const int* __restrict__ qtok,
                  const float* __restrict__ w,
                  const float* __restrict__ bias,
                  float* __restrict__ out) {
    const int b    = blockIdx.x * 8 + (threadIdx.x >> 5);
    const int lane = threadIdx.x & 31;
    float sum = 0.f;
    for (int idx = lane; idx < Q_ * K_; idx += 32) {
        const int q = idx / K_, k = idx % K_;
        float s = 0.f;
        #pragma unroll
        for (int m = 0; m < NMT; ++m)
            s += g_part[((long)(b * NMT + m)) * (Q_ * K_) + idx];
        const float qm = (qtok[b * Q_ + q] > 0) ? 1.f : 0.f;
        sum += 0.01f * __logf(fmaxf(s, 1e-10f)) * qm * __ldg(&w[k]);
    }
    #pragma unroll
    for (int off = 16; off; off >>= 1) sum += __shfl_xor_sync(0xffffffffu, sum, off);
    if (lane == 0) out[b] = sum + bias[0];
}

// ---------------------------------------------------------------------------
extern "C" void kernel_launch(void* const* d_in, const int* in_sizes, int n_in,
                              void* d_out, int out_size) {
    const int*   qtok  = (const int*)d_in[0];    // [256,32]
    const int*   dtok  = (const int*)d_in[1];    // [256,512]
    const float* emb   = (const float*)d_in[2];  // [100000,300]
    const float* w     = (const float*)d_in[3];  // [1,11]
    const float* bias  = (const float*)d_in[4];  // [1]
    const float* mu    = (const float*)d_in[5];  // [11]
    const float* sigma = (const float*)d_in[6];  // [11]
    float* out = (float*)d_out;                  // [256]

    static bool attr_set = false;
    if (!attr_set) {
        cudaFuncSetAttribute(knrm_main_kernel,
                             cudaFuncAttributeMaxDynamicSharedMemorySize,
                             (int)sizeof(SM));
        attr_set = true;
    }
    norm_emb_kernel<<<(V_ + 7) / 8, 256>>>(emb);
    knrm_main_kernel<<<B_ * NMT, 256, sizeof(SM)>>>(qtok, dtok, mu, sigma);
    knrm_final_kernel<<<B_ / 8, 256>>>(qtok, w, bias, out);
}

// round 11
// speedup vs baseline: 2.2772x; 1.0040x over previous
#include <cuda_runtime.h>
#include <cuda_fp16.h>
#include <cstdint>
#include <math.h>

#define B_     256
#define Q_     32
#define D_     512
#define E_     300
#define K_     11
#define V_     100000
#define EPH    304       // table row length (halves)
#define ROWB   608       // table row bytes
#define SROWH  312       // smem row stride (halves) = 624 B, conflict-free
#define SROWB  624
#define MT_    128       // docs per CTA
#define NMT    4
#define NKS    19        // 304 / 16 k-steps

#define EX2F(r, x) asm("ex2.approx.f32 %0, %1;" : "=f"(r) : "f"(x))

__device__ __align__(256) __half g_ne[(size_t)V_ * EPH];  // normalized fp16 table (60.8 MB)
__device__ unsigned char g_used[102400];                  // token-used flags
__device__ float g_part[B_ * NMT * Q_ * K_];

// ---------------- PTX helpers ----------------
#define MBAR_INIT(mb, c) asm volatile("mbarrier.init.shared.b64 [%0], %1;" :: "r"((uint32_t)(mb)), "r"((uint32_t)(c)) : "memory")
#define MBAR_ARRIVE_EXPECT(mb, bytes) asm volatile("mbarrier.arrive.expect_tx.shared.b64 _, [%0], %1;" :: "r"((uint32_t)(mb)), "r"((uint32_t)(bytes)) : "memory")
#define MBAR_WAIT(mb, ph) do {                                               \
    uint32_t _m = (uint32_t)(mb), _p = (uint32_t)(ph), _d;                   \
    asm volatile("{\n\t.reg .pred p;\n\t"                                    \
        "mbarrier.try_wait.parity.acquire.cta.shared::cta.b64 p, [%1], %2;\n\t" \
        "selp.b32 %0, 1, 0, p;\n\t}" : "=r"(_d) : "r"(_m), "r"(_p) : "memory"); \
    if (!_d) {                                                               \
        asm volatile("{\n\t.reg .pred P1;\n\t"                               \
            "W%=:\n\t"                                                       \
            "mbarrier.try_wait.parity.acquire.cta.shared::cta.b64 P1, [%0], %1, 0x989680;\n\t" \
            "@P1 bra.uni WD%=;\n\t"                                          \
            "bra.uni W%=;\n\t"                                               \
            "WD%=:\n\t}" :: "r"(_m), "r"(_p) : "memory");                    \
    }                                                                        \
} while (0)
#define BULK(dst, src, n, mb) \
    asm volatile("cp.async.bulk.shared::cluster.global.mbarrier::complete_tx::bytes [%0], [%1], %2, [%3];" \
        :: "r"((uint32_t)(dst)), "l"(src), "r"((uint32_t)(n)), "r"((uint32_t)(mb)) : "memory")

__device__ __forceinline__ void hmma16816(float* c, const uint32_t* a, const uint32_t* b) {
    asm volatile("mma.sync.aligned.m16n8k16.row.col.f32.f16.f16.f32 "
        "{%0,%1,%2,%3}, {%4,%5,%6,%7}, {%8,%9}, {%0,%1,%2,%3};"
        : "+f"(c[0]), "+f"(c[1]), "+f"(c[2]), "+f"(c[3])
        : "r"(a[0]), "r"(a[1]), "r"(a[2]), "r"(a[3]), "r"(b[0]), "r"(b[1]));
}

// ---------------------------------------------------------------------------
// Pass 0a: clear used-token flags (25 blocks x 256, uint4 stores)
// ---------------------------------------------------------------------------
__global__ void clear_flags_kernel() {
    const int i = blockIdx.x * 256 + threadIdx.x;     // 6400 threads x 16B
    ((uint4*)g_used)[i] = make_uint4(0u, 0u, 0u, 0u);
}

// ---------------------------------------------------------------------------
// Pass 0b: mark referenced tokens
// ---------------------------------------------------------------------------
__global__ void mark_flags_kernel(const int* __restrict__ qtok,
                                  const int* __restrict__ dtok) {
    const int i = blockIdx.x * 256 + threadIdx.x;     // 139264 threads
    const int t = (i < B_ * Q_) ? qtok[i] : dtok[i - B_ * Q_];
    g_used[t] = 1;
}

// ---------------------------------------------------------------------------
// Pass 1: normalize used embedding rows -> fp16 table (304 halves/row).
// Warp per row, float4 loads.
// ---------------------------------------------------------------------------
__global__ void __launch_bounds__(256)
norm_emb_kernel(const float* __restrict__ emb) {
    const int row  = blockIdx.x * 8 + (threadIdx.x >> 5);
    const int lane = threadIdx.x & 31;
    if (row >= V_) return;
    if (!g_used[row]) return;
    const float* src = emb + (long)row * E_;
    float4 v[3];
    float s = 0.f;
    #pragma unroll
    for (int i = 0; i < 3; ++i) {
        const int e = 4 * lane + 128 * i;
        if (e < E_) {
            v[i] = *(const float4*)(src + e);
            s = fmaf(v[i].x, v[i].x, s); s = fmaf(v[i].y, v[i].y, s);
            s = fmaf(v[i].z, v[i].z, s); s = fmaf(v[i].w, v[i].w, s);
        } else {
            v[i] = make_float4(0.f, 0.f, 0.f, 0.f);
        }
    }
    #pragma unroll
    for (int off = 16; off; off >>= 1) s += __shfl_xor_sync(0xffffffffu, s, off);
    const float iv = 1.f / (sqrtf(s) + 1e-13f);
    __half* dst = g_ne + (size_t)row * EPH;
    #pragma unroll
    for (int i = 0; i < 3; ++i) {
        const int e = 4 * lane + 128 * i;
        if (e < EPH) {   // e=300 lane writes padded zeros (v = 0 there)
            __half2 h0 = __floats2half2_rn(v[i].x * iv, v[i].y * iv);
            __half2 h1 = __floats2half2_rn(v[i].z * iv, v[i].w * iv);
            uint2 pk = make_uint2(*(uint32_t*)&h0, *(uint32_t*)&h1);
            *(uint2*)(dst + e) = pk;
        }
    }
}

// ---------------------------------------------------------------------------
// Main kernel: TMA-bulk row gather + fp16 HMMA cosine GEMM (128 docs x 32 q,
// K=304) + Gaussian kernels + exact-match K0. Grid 1024, 256 threads.
// ---------------------------------------------------------------------------
struct SM {
    __align__(16) __half A[MT_ * SROWH];        // 79,872 B
    union {
        __align__(16) __half Bq[Q_ * SROWH];    // 19,968 B
        float spart[8][Q_][12];                 // 12,288 B (after mainloop)
    } u;
    float dm[MT_];
    int   dtk[MT_];
    float qm[Q_];
    int   qt[Q_];
    float mu[K_], nis[K_];
    __align__(8) unsigned long long mbarA[8], mbarB;
};

__global__ void __launch_bounds__(256, 2)
knrm_main_kernel(const int* __restrict__ qtok,
                 const int* __restrict__ dtok,
                 const float* __restrict__ mu,
                 const float* __restrict__ sigma) {
    extern __shared__ char smem_raw[];
    SM& sm = *reinterpret_cast<SM*>(smem_raw);

    const int bi = blockIdx.x, b = bi >> 2, mt = bi & 3;
    const int tid = threadIdx.x, w = tid >> 5, lane = tid & 31;

    if (tid < Q_) { int t = qtok[b * Q_ + tid]; sm.qt[tid] = t; sm.qm[tid] = (t > 0) ? 1.f : 0.f; }
    if (tid >= 64 && tid < 64 + K_) {
        const int k = tid - 64;
        float sg = sigma[k];
        sm.mu[k]  = mu[k];
        sm.nis[k] = -1.4426950408889634f / (2.f * sg * sg);
    }
    if (tid >= 128) {
        const int dc = tid - 128;
        int t = dtok[b * D_ + mt * MT_ + dc];
        sm.dtk[dc] = t; sm.dm[dc] = (t > 0) ? 1.f : 0.f;
    }
    if (tid == 0) {
        #pragma unroll
        for (int i = 0; i < 8; ++i) MBAR_INIT((uint32_t)__cvta_generic_to_shared(&sm.mbarA[i]), 1);
        MBAR_INIT((uint32_t)__cvta_generic_to_shared(&sm.mbarB), 8);
    }
    __syncthreads();

    const uint32_t aBase = (uint32_t)__cvta_generic_to_shared(sm.A);
    const uint32_t bBase = (uint32_t)__cvta_generic_to_shared(sm.u.Bq);
    const uint32_t mbB   = (uint32_t)__cvta_generic_to_shared(&sm.mbarB);
    const uint32_t mbA   = (uint32_t)__cvta_generic_to_shared(&sm.mbarA[w]);
    const char* ne = (const char*)g_ne;

    if (lane == 0) {
        MBAR_ARRIVE_EXPECT(mbB, 4 * ROWB);
        #pragma unroll
        for (int r = 0; r < 4; ++r) {
            const int q = 4 * w + r;
            BULK(bBase + q * SROWB, ne + (size_t)sm.qt[q] * ROWB, ROWB, mbB);
        }
        MBAR_ARRIVE_EXPECT(mbA, 16 * ROWB);
        #pragma unroll
        for (int r = 0; r < 16; ++r) {
            const int d = 16 * w + r;
            BULK(aBase + d * SROWB, ne + (size_t)sm.dtk[d] * ROWB, ROWB, mbA);
        }
    }
    MBAR_WAIT(mbB, 0);
    MBAR_WAIT(mbA, 0);

    // ---- HMMA mainloop: warp w owns docs [16w,16w+16), all K in smem ----
    float acc[4][4];
    #pragma unroll
    for (int t = 0; t < 4; ++t)
        #pragma unroll
        for (int i = 0; i < 4; ++i) acc[t][i] = 0.f;

    const int r4 = lane >> 2, c2 = (lane & 3) * 2;
    const __half* arow0 = sm.A + (16 * w + r4) * SROWH;
    const __half* arow1 = arow0 + 8 * SROWH;

    #pragma unroll
    for (int ks = 0; ks < NKS; ++ks) {
        const int k0 = ks * 16 + c2;
        uint32_t a[4];
        a[0] = *(const uint32_t*)&arow0[k0];
        a[1] = *(const uint32_t*)&arow1[k0];
        a[2] = *(const uint32_t*)&arow0[k0 + 8];
        a[3] = *(const uint32_t*)&arow1[k0 + 8];
        #pragma unroll
        for (int t = 0; t < 4; ++t) {
            const __half* brow = sm.u.Bq + (t * 8 + r4) * SROWH;
            uint32_t bb[2];
            bb[0] = *(const uint32_t*)&brow[k0];
            bb[1] = *(const uint32_t*)&brow[k0 + 8];
            hmma16816(acc[t], a, bb);
        }
    }
    __syncthreads();   // all warps done reading Bq before spart overlays it

    // ---- epilogue: Gaussian kernels + exact-match K0 ----
    const int doc0 = 16 * w + r4, doc1 = doc0 + 8;
    const float dm0 = sm.dm[doc0], dm1 = sm.dm[doc1];
    const int   tk0 = sm.dtk[doc0], tk1 = sm.dtk[doc1];

    #pragma unroll
    for (int t = 0; t < 4; ++t) {
        const int q0 = t * 8 + c2, q1 = q0 + 1;
        const float qm0 = sm.qm[q0], qm1 = sm.qm[q1];
        const int   tq0 = sm.qt[q0], tq1 = sm.qt[q1];
        const float m00 = qm0 * dm0, m01 = qm1 * dm0;
        const float m10 = qm0 * dm1, m11 = qm1 * dm1;
        const float c00 = acc[t][0] * m00, c01 = acc[t][1] * m01;  // masked cosine
        const float c10 = acc[t][2] * m10, c11 = acc[t][3] * m11;

        float pk0[K_], pk1[K_];
        pk0[0] = ((tq0 > 0) ? (((tk0 == tq0) ? 1.f : 0.f) + ((tk1 == tq0) ? 1.f : 0.f)) : 0.f);
        pk1[0] = ((tq1 > 0) ? (((tk0 == tq1) ? 1.f : 0.f) + ((tk1 == tq1) ? 1.f : 0.f)) : 0.f);
        #pragma unroll
        for (int k = 1; k < K_; ++k) {
            const float muk = sm.mu[k], nk = sm.nis[k];
            float d00 = c00 - muk, d01 = c01 - muk, d10 = c10 - muk, d11 = c11 - muk;
            float e00, e01, e10, e11;
            EX2F(e00, d00 * nk * d00); EX2F(e01, d01 * nk * d01);
            EX2F(e10, d10 * nk * d10); EX2F(e11, d11 * nk * d11);
            pk0[k] = fmaf(m00, e00, m10 * e10);
            pk1[k] = fmaf(m01, e01, m11 * e11);
        }
        #pragma unroll
        for (int k = 0; k < K_; ++k) {
            float v0 = pk0[k], v1 = pk1[k];
            v0 += __shfl_xor_sync(0xffffffffu, v0, 4);
            v0 += __shfl_xor_sync(0xffffffffu, v0, 8);
            v0 += __shfl_xor_sync(0xffffffffu, v0, 16);
            v1 += __shfl_xor_sync(0xffffffffu, v1, 4);
            v1 += __shfl_xor_sync(0xffffffffu, v1, 8);
            v1 += __shfl_xor_sync(0xffffffffu, v1, 16);
            if (lane < 4) { sm.u.spart[w][q0][k] = v0; sm.u.spart[w][q1][k] = v1; }
        }
    }
    __syncthreads();

    for (int idx = tid; idx < Q_ * K_; idx += 256) {
        const int q = idx / K_, k = idx % K_;
        float s = 0.f;
        #pragma unroll
        for (int ww = 0; ww < 8; ++ww) s += sm.u.spart[ww][q][k];
        g_part[(long)bi * (Q_ * K_) + idx] = s;
    }
}

// ---------------------------------------------------------------------------
// Final: warp per batch. Grid 32 x 256.
// ---------------------------------------------------------------------------
__global__ void __launch_bounds__(256)
knrm_final_kernel(const int* __restrict__ qtok,
                  const float* __restrict__ w,
                  const float* __restrict__ bias,
                  float* __restrict__ out) {
    const int b    = blockIdx.x * 8 + (threadIdx.x >> 5);
    const int lane = threadIdx.x & 31;
    float sum = 0.f;
    for (int idx = lane; idx < Q_ * K_; idx += 32) {
        const int q = idx / K_, k = idx % K_;
        float s = 0.f;
        #pragma unroll
        for (int m = 0; m < NMT; ++m)
            s += g_part[((long)(b * NMT + m)) * (Q_ * K_) + idx];
        const float qm = (qtok[b * Q_ + q] > 0) ? 1.f : 0.f;
        sum += 0.01f * __logf(fmaxf(s, 1e-10f)) * qm * __ldg(&w[k]);
    }
    #pragma unroll
    for (int off = 16; off; off >>= 1) sum += __shfl_xor_sync(0xffffffffu, sum, off);
    if (lane == 0) out[b] = sum + bias[0];
}

// ---------------------------------------------------------------------------
extern "C" void kernel_launch(void* const* d_in, const int* in_sizes, int n_in,
                              void* d_out, int out_size) {
    const int*   qtok  = (const int*)d_in[0];    // [256,32]
    const int*   dtok  = (const int*)d_in[1];    // [256,512]
    const float* emb   = (const float*)d_in[2];  // [100000,300]
    const float* w     = (const float*)d_in[3];  // [1,11]
    const float* bias  = (const float*)d_in[4];  // [1]
    const float* mu    = (const float*)d_in[5];  // [11]
    const float* sigma = (const float*)d_in[6];  // [11]
    float* out = (float*)d_out;                  // [256]

    static bool attr_set = false;
    if (!attr_set) {
        cudaFuncSetAttribute(knrm_main_kernel,
                             cudaFuncAttributeMaxDynamicSharedMemorySize,
                             (int)sizeof(SM));
        attr_set = true;
    }
    clear_flags_kernel<<<25, 256>>>();
    mark_flags_kernel<<<(B_ * Q_ + B_ * D_) / 256, 256>>>(qtok, dtok);
    norm_emb_kernel<<<(V_ + 7) / 8, 256>>>(emb);
    knrm_main_kernel<<<B_ * NMT, 256, sizeof(SM)>>>(qtok, dtok, mu, sigma);
    knrm_final_kernel<<<B_ / 8, 256>>>(qtok, w, bias, out);
}